// round 4
// baseline (speedup 1.0000x reference)
#include <cuda_runtime.h>
#include <cuda_bf16.h>

#define NATOMS 256
#define NMOL   4
#define NPAIRS 8192
#define NPAIRC 32640              // 256*255/2 unordered coulomb pairs
#define NGRP   (NPAIRC + 1)       // + diag-constant group
#define NBLK_PAIR ((NGRP + 31) / 32)
#define KEC      14.3996f
#define AA       0.3f
#define PI_F     3.14159265358979323846f
#define SQRTPI_F 1.7724538509055160273f
#define TWOPI_F  6.2831853071795864769f
#define INV2A      (1.0f/(2.0f*AA))
#define TWOA_SQPI  (2.0f*AA/SQRTPI_F)
#define FOURA_SQPI (4.0f*AA/SQRTPI_F)
#define INV_A_SQPI (1.0f/(AA*SQRTPI_F))

__device__ float  g_Rs[NATOMS][3];
__device__ float  g_G[NATOMS][3];        // dE_total/dR (coulomb x8 + born)
__device__ float  g_U[NATOMS][6];        // Sum_j H_aj   (coulomb x8 + born)
__device__ float  g_T[NATOMS*NMOL][6];   // Sum_{j in m, film} H_aj
__device__ int    g_fm[NATOMS];          // film ? mol : -1
__device__ double g_Ec;
__device__ double g_Eb[NMOL];

__device__ __forceinline__ float blockReduce256(float v, float* sh) {
    const unsigned full = 0xffffffffu;
    #pragma unroll
    for (int o = 16; o > 0; o >>= 1) v += __shfl_down_sync(full, v, o);
    int lane = threadIdx.x & 31, w = threadIdx.x >> 5;
    if (lane == 0) sh[w] = v;
    __syncthreads();
    float r = 0.f;
    if (w == 0) {
        r = (lane < 8) ? sh[lane] : 0.f;
        #pragma unroll
        for (int o = 4; o > 0; o >>= 1) r += __shfl_down_sync(full, r, o);
    }
    __syncthreads();
    return r;
}

// erfc(x)*exp(x*x) for x>=0 (A&S 7.1.26)
__device__ __forceinline__ float erfcx_p(float x) {
    float t = __frcp_rn(fmaf(0.3275911f, x, 1.0f));
    float p = fmaf(t, 1.061405429f, -1.453152027f);
    p = fmaf(t, p, 1.421413741f);
    p = fmaf(t, p, -0.284496736f);
    p = fmaf(t, p, 0.254829592f);
    return t * p;
}

__device__ __forceinline__ void Ffuncs(float d2, float z, float az, float azsq,
                                       float& F, float& Fz, float& Fzz) {
    float d  = sqrtf(d2);
    float u  = d * INV2A;
    float dz = d * z;
    float g  = __expf(-fmaf(u, u, azsq));
    float x1 = u + az, x2 = u - az;
    float e1 = g * erfcx_p(fabsf(x1));
    float e2 = g * erfcx_p(fabsf(x2));
    if (x1 < 0.f) e1 = 2.f * __expf(dz)  - e1;
    if (x2 < 0.f) e2 = 2.f * __expf(-dz) - e2;
    float s = e1 + e2;
    F   = __fdividef(s, d);
    Fz  = e1 - e2;
    Fzz = fmaf(d, s, -FOURA_SQPI * g);
}

__global__ void k_prep(const float* __restrict__ R, const float* __restrict__ shift,
                       const int* __restrict__ idx_m, const int* __restrict__ is_film) {
    int a = threadIdx.x;
    int m = idx_m[a];
    float f = (is_film[a] > 0) ? 1.f : 0.f;
    g_fm[a] = (is_film[a] > 0) ? m : -1;
    #pragma unroll
    for (int c = 0; c < 3; c++) {
        g_Rs[a][c] = R[a * 3 + c] + f * shift[m * 3 + c];
        g_G[a][c] = 0.f;
    }
    #pragma unroll
    for (int c = 0; c < 6; c++) g_U[a][c] = 0.f;
    #pragma unroll
    for (int m2 = 0; m2 < NMOL; m2++)
        #pragma unroll
        for (int c = 0; c < 6; c++) g_T[a * NMOL + m2][c] = 0.f;
    if (a == 0) g_Ec = 0.0;
    if (a < NMOL) g_Eb[a] = 0.0;
}

__global__ void __launch_bounds__(256) k_main(const float* __restrict__ q,
                                              const float* __restrict__ cell,
                                              const float* __restrict__ recip,
                                              const float* __restrict__ off,
                                              const float* __restrict__ r0_,
                                              const float* __restrict__ n_,
                                              const int* __restrict__ ii,
                                              const int* __restrict__ jj,
                                              const int* __restrict__ mm) {
    int t = threadIdx.x;
    if (blockIdx.x < NBLK_PAIR) {
        int g = blockIdx.x * 32 + (t >> 3);
        int r = t & 7;
        bool isDiag = (g == NPAIRC);
        bool isPair = (g < NPAIRC);
        int i = 0, j = 0, fmi = -1, fmj = -1;

        float E = 0.f, Gx = 0.f, Gy = 0.f, Gz = 0.f;
        float H0 = 0.f, H1 = 0.f, H2 = 0.f, H3 = 0.f, H4 = 0.f, H5 = 0.f;
        float Sq2 = 0.f;

        if (isPair || isDiag) {
            float dx = 0.f, dy = 0.f, dz = 0.f, qq = 1.f, wE = 1.f;
            if (isPair) {
                int b = g / 255, k = g % 255;
                int n1 = 255 - b;
                if (k < n1) { i = b;       j = b + 1 + k; }
                else        { i = 255 - b; j = i + 1 + (k - n1); }
                dx = g_Rs[i][0] - g_Rs[j][0];
                dy = g_Rs[i][1] - g_Rs[j][1];
                dz = g_Rs[i][2] - g_Rs[j][2];
                qq = q[i] * q[j];
                fmi = g_fm[i]; fmj = g_fm[j];
                wE = 2.f;
            } else {
                #pragma unroll
                for (int k2 = 0; k2 < 32; k2++) {
                    float qa = q[r * 32 + k2];
                    Sq2 = fmaf(qa, qa, Sq2);
                }
            }

            float c0x = cell[0], c0y = cell[1], c0z = cell[2];
            float c1x = cell[3], c1y = cell[4], c1z = cell[5];
            float crx = c0y * c1z - c0z * c1y;
            float cry = c0z * c1x - c0x * c1z;
            float crz = c0x * c1y - c0y * c1x;
            float area = sqrtf(crx * crx + cry * cry + crz * crz);
            float K0x = TWOPI_F * recip[0], K0y = TWOPI_F * recip[1], K0z = TWOPI_F * recip[2];
            float K1x = TWOPI_F * recip[3], K1y = TWOPI_F * recip[4], K1z = TWOPI_F * recip[5];

            float az = AA * dz, azsq = az * az;
            float alpha = K0x * dx + K0y * dy + K0z * dz;
            float beta  = K1x * dx + K1y * dy + K1z * dz;

            float Ek = 0.f, Gkx = 0.f, Gky = 0.f, Gkz = 0.f;
            float Kxx = 0.f, Kyy = 0.f, Kzz = 0.f, Kxy = 0.f, Kxz = 0.f, Kyz = 0.f;
            float Er = 0.f, Grx = 0.f, Gry = 0.f, Grz = 0.f;
            float Rxx = 0.f, Ryy = 0.f, Rzz = 0.f, Rxy = 0.f, Rxz = 0.f, Ryz = 0.f;

            auto accum = [&](float cT, float sT, float hx, float hy, float hz,
                             float F, float Fz, float Fzz) {
                float cF  = cT * F;
                float sF  = sT * F;
                float sFz = sT * Fz;
                Ek  += cF;
                Gkx -= sF * hx;
                Gky -= sF * hy;
                Gkz += cT * Fz - sF * hz;
                Kxx -= cF * hx * hx;
                Kyy -= cF * hy * hy;
                Kxy -= cF * hx * hy;
                Kxz -= cF * hx * hz + sFz * hx;
                Kyz -= cF * hy * hz + sFz * hy;
                Kzz += cT * Fzz - cF * hz * hz - 2.f * sFz * hz;
            };

            if (r < 7) {
                float fr = (float)r;
                float sA, cA, sb, cb;
                sincosf(fr * alpha, &sA, &cA);
                sincosf(beta, &sb, &cb);
                float h0x = fr * K0x, h0y = fr * K0y, h0z = fr * K0z;
                if (r > 0) {
                    float d2 = h0x * h0x + h0y * h0y + h0z * h0z;
                    float F, Fz, Fzz; Ffuncs(d2, dz, az, azsq, F, Fz, Fzz);
                    accum(cA, sA, h0x, h0y, h0z, F, Fz, Fzz);
                }
                float cB = cb, sB = sb;
                float hpx = h0x + K1x, hpy = h0y + K1y, hpz = h0z + K1z;
                float hmx = h0x - K1x, hmy = h0y - K1y, hmz = h0z - K1z;
                #pragma unroll 1
                for (int j1 = 1; j1 <= 6; j1++) {
                    float d2p = hpx * hpx + hpy * hpy + hpz * hpz;
                    float F, Fz, Fzz; Ffuncs(d2p, dz, az, azsq, F, Fz, Fzz);
                    float cP = cA * cB - sA * sB, sP = sA * cB + cA * sB;
                    accum(cP, sP, hpx, hpy, hpz, F, Fz, Fzz);
                    if (r > 0) {
                        float d2m = hmx * hmx + hmy * hmy + hmz * hmz;
                        float Fm = F, Fzm = Fz, Fzzm = Fzz;
                        if (d2m != d2p) Ffuncs(d2m, dz, az, azsq, Fm, Fzm, Fzzm);
                        float cM = cA * cB + sA * sB, sM = sA * cB - cA * sB;
                        accum(cM, sM, hmx, hmy, hmz, Fm, Fzm, Fzzm);
                    }
                    float cBn = cB * cb - sB * sb;
                    sB = sB * cb + cB * sb;
                    cB = cBn;
                    hpx += K1x; hpy += K1y; hpz += K1z;
                    hmx -= K1x; hmy -= K1y; hmz -= K1z;
                }
                if (r == 0) {  // S2 term
                    float egz  = __expf(-azsq);
                    float erfz = copysignf(1.f - erfcx_p(fabsf(az)) * egz, az);
                    Ek  -= dz * erfz + egz * INV_A_SQPI;
                    Gkz -= erfz;
                    Kzz -= TWOA_SQPI * egz;
                }
            }
            // real-space images: lane 0 -> [0,12), lane 7 -> [12,25)
            int s0 = (r == 0) ? 0 : 12, s1 = (r == 0 || r == 7) ? ((r == 0) ? 12 : 25) : 12;
            #pragma unroll 1
            for (int idx = s0; idx < s1; idx++) {
                float fn0 = (float)(idx / 5 - 2), fn1 = (float)(idx % 5 - 2);
                float rx = dx + fn0 * c0x + fn1 * c1x;
                float ry = dy + fn0 * c0y + fn1 * c1y;
                float rz = dz + fn0 * c0z + fn1 * c1z;
                float dd = rx * rx + ry * ry + rz * rz;
                if (dd > 0.f && dd < (81.0f / (AA * AA))) {
                    float dr    = sqrtf(dd);
                    float ad    = AA * dr;
                    float e     = __expf(-ad * ad);
                    float tt    = erfcx_p(ad) * e;
                    float invd  = __fdividef(1.f, dr);
                    float invd2 = invd * invd;
                    Er += tt * invd;
                    float up  = -(TWOA_SQPI * e + tt * invd) * invd;
                    float upp = TWOA_SQPI * e * (2.f * AA * AA + 2.f * invd2) + 2.f * tt * invd * invd2;
                    float s1v = up * invd;
                    Grx += s1v * rx; Gry += s1v * ry; Grz += s1v * rz;
                    float w = (upp - s1v) * invd2;
                    Rxx += w * rx * rx + s1v;
                    Ryy += w * ry * ry + s1v;
                    Rzz += w * rz * rz + s1v;
                    Rxy += w * rx * ry;
                    Rxz += w * rx * rz;
                    Ryz += w * ry * rz;
                }
            }

            float pk = qq * (KEC * PI_F / area);
            float p3 = qq * (0.5f * KEC);
            E  = wE * (pk * Ek + p3 * Er);
            Gx = pk * Gkx + p3 * Grx;
            Gy = pk * Gky + p3 * Gry;
            Gz = pk * Gkz + p3 * Grz;
            H0 = pk * Kxx + p3 * Rxx;
            H1 = pk * Kyy + p3 * Ryy;
            H2 = pk * Kzz + p3 * Rzz;
            H3 = pk * Kxy + p3 * Rxy;
            H4 = pk * Kxz + p3 * Rxz;
            H5 = pk * Kyz + p3 * Ryz;
        }

        // 8-lane butterfly: all lanes end with the group totals
        const unsigned full = 0xffffffffu;
        #pragma unroll
        for (int o = 1; o < 8; o <<= 1) {
            E   += __shfl_xor_sync(full, E, o);
            Gx  += __shfl_xor_sync(full, Gx, o);
            Gy  += __shfl_xor_sync(full, Gy, o);
            Gz  += __shfl_xor_sync(full, Gz, o);
            H0  += __shfl_xor_sync(full, H0, o);
            H1  += __shfl_xor_sync(full, H1, o);
            H2  += __shfl_xor_sync(full, H2, o);
            H3  += __shfl_xor_sync(full, H3, o);
            H4  += __shfl_xor_sync(full, H4, o);
            H5  += __shfl_xor_sync(full, H5, o);
            Sq2 += __shfl_xor_sync(full, Sq2, o);
        }

        if (isPair) {
            if (r < 6) {
                float h = (r == 0) ? H0 : (r == 1) ? H1 : (r == 2) ? H2 :
                          (r == 3) ? H3 : (r == 4) ? H4 : H5;
                h *= 8.f;
                atomicAdd(&g_U[i][r], h);
                atomicAdd(&g_U[j][r], h);
                if (fmj >= 0) atomicAdd(&g_T[i * NMOL + fmj][r], h);
                if (fmi >= 0) atomicAdd(&g_T[j * NMOL + fmi][r], h);
            } else if (r == 6) {
                atomicAdd(&g_G[i][0], 8.f * Gx);
                atomicAdd(&g_G[i][1], 8.f * Gy);
                atomicAdd(&g_G[i][2], 8.f * Gz);
            } else {
                atomicAdd(&g_G[j][0], -8.f * Gx);
                atomicAdd(&g_G[j][1], -8.f * Gy);
                atomicAdd(&g_G[j][2], -8.f * Gz);
            }
        }

        float myE = isDiag ? E * Sq2 * 0.125f : E * 0.125f;
        __shared__ float red[32];
        float se = blockReduce256(myE, red);
        if (t == 0) atomicAdd(&g_Ec, (double)se);
    } else {
        // -------- born pairs --------
        int p = (blockIdx.x - NBLK_PAIR) * 256 + t;
        __shared__ float sE[NMOL];
        if (t < NMOL) sE[t] = 0.f;
        __syncthreads();

        int i = ii[p], j = jj[p];
        float rx = g_Rs[j][0] - g_Rs[i][0] + off[p * 3 + 0];
        float ry = g_Rs[j][1] - g_Rs[i][1] + off[p * 3 + 1];
        float rz = g_Rs[j][2] - g_Rs[i][2] + off[p * 3 + 2];
        float d2 = rx * rx + ry * ry + rz * rz;
        float d  = sqrtf(d2);

        if (d < 6.0f) {
            float n  = n_[p], r0 = r0_[p];
            float qq = fabsf(q[i] * q[j]);
            float B  = qq * __powf(r0, n - 1.f) * __fdividef(1.f, n);
            float dn = __powf(d, -n);
            float cn = __powf(6.0f, -n);
            float y  = B * (dn - cn);
            atomicAdd(&sE[mm[i]], 0.5f * KEC * y);
            float f     = 0.5f * KEC;
            float invd  = __fdividef(1.f, d);
            float invd2 = invd * invd;
            float yp  = -n * B * dn * invd;
            float ypp = n * (n + 1.f) * B * dn * invd2;
            float s1  = f * yp * invd;
            atomicAdd(&g_G[j][0],  s1 * rx);
            atomicAdd(&g_G[j][1],  s1 * ry);
            atomicAdd(&g_G[j][2],  s1 * rz);
            atomicAdd(&g_G[i][0], -s1 * rx);
            atomicAdd(&g_G[i][1], -s1 * ry);
            atomicAdd(&g_G[i][2], -s1 * rz);
            float w = (f * ypp - s1) * invd2;
            float Hxx = w * rx * rx + s1, Hyy = w * ry * ry + s1, Hzz = w * rz * rz + s1;
            float Hxy = w * rx * ry, Hxz = w * rx * rz, Hyz = w * ry * rz;
            atomicAdd(&g_U[i][0], Hxx); atomicAdd(&g_U[j][0], Hxx);
            atomicAdd(&g_U[i][1], Hyy); atomicAdd(&g_U[j][1], Hyy);
            atomicAdd(&g_U[i][2], Hzz); atomicAdd(&g_U[j][2], Hzz);
            atomicAdd(&g_U[i][3], Hxy); atomicAdd(&g_U[j][3], Hxy);
            atomicAdd(&g_U[i][4], Hxz); atomicAdd(&g_U[j][4], Hxz);
            atomicAdd(&g_U[i][5], Hyz); atomicAdd(&g_U[j][5], Hyz);
            int fmi = g_fm[i], fmj = g_fm[j];
            if (fmj >= 0) {
                float* Tp = g_T[i * NMOL + fmj];
                atomicAdd(&Tp[0], Hxx); atomicAdd(&Tp[1], Hyy); atomicAdd(&Tp[2], Hzz);
                atomicAdd(&Tp[3], Hxy); atomicAdd(&Tp[4], Hxz); atomicAdd(&Tp[5], Hyz);
            }
            if (fmi >= 0) {
                float* Tp = g_T[j * NMOL + fmi];
                atomicAdd(&Tp[0], Hxx); atomicAdd(&Tp[1], Hyy); atomicAdd(&Tp[2], Hzz);
                atomicAdd(&Tp[3], Hxy); atomicAdd(&Tp[4], Hxz); atomicAdd(&Tp[5], Hyz);
            }
        }
        __syncthreads();
        if (t < NMOL) atomicAdd(&g_Eb[t], (double)sE[t]);
    }
}

__global__ void k_fin(const float* __restrict__ q, const int* __restrict__ idx_m,
                      const int* __restrict__ is_film, float* __restrict__ out) {
    int a = threadIdx.x;
    __shared__ float sff[NMOL * 3];
    __shared__ float sfn[NMOL * 3];
    __shared__ float red[32];
    if (a < NMOL * 3) { sff[a] = 0.f; sfn[a] = 0.f; }
    __syncthreads();

    float Fx = -g_G[a][0], Fy = -g_G[a][1], Fz = -g_G[a][2];
    int m = idx_m[a];
    bool film = (is_film[a] > 0);
    if (film) {
        atomicAdd(&sff[m * 3 + 0], Fx);
        atomicAdd(&sff[m * 3 + 1], Fy);
        atomicAdd(&sff[m * 3 + 2], Fz);
    }
    float qa = q[a];
    float sq2 = blockReduce256(qa * qa, red);  // syncthreads inside makes sff visible

    // HVP: Hv_a = U_a * v_a - Sum_m T_am * ff_m
    float vx = film ? sff[m * 3 + 0] : 0.f;
    float vy = film ? sff[m * 3 + 1] : 0.f;
    float vz = film ? sff[m * 3 + 2] : 0.f;
    float U0 = g_U[a][0], U1 = g_U[a][1], U2 = g_U[a][2];
    float U3 = g_U[a][3], U4 = g_U[a][4], U5 = g_U[a][5];
    float Hvx = U0 * vx + U3 * vy + U4 * vz;
    float Hvy = U3 * vx + U1 * vy + U5 * vz;
    float Hvz = U4 * vx + U5 * vy + U2 * vz;
    #pragma unroll
    for (int m2 = 0; m2 < NMOL; m2++) {
        const float* Tp = g_T[a * NMOL + m2];
        float fx = sff[m2 * 3 + 0], fy = sff[m2 * 3 + 1], fz = sff[m2 * 3 + 2];
        Hvx -= Tp[0] * fx + Tp[3] * fy + Tp[4] * fz;
        Hvy -= Tp[3] * fx + Tp[1] * fy + Tp[5] * fz;
        Hvz -= Tp[4] * fx + Tp[5] * fy + Tp[2] * fz;
    }
    if (film) {
        atomicAdd(&sfn[m * 3 + 0], Hvx);
        atomicAdd(&sfn[m * 3 + 1], Hvy);
        atomicAdd(&sfn[m * 3 + 2], Hvz);
    }
    __syncthreads();

    if (a == 0) {
        float self = -(AA / SQRTPI_F) * KEC * sq2;
        float yc = (float)g_Ec + self;
        out[4] = yc;
        #pragma unroll
        for (int m2 = 0; m2 < NMOL; m2++) {
            float yb = (float)g_Eb[m2];
            out[m2]     = yc + yb;
            out[5 + m2] = yb;
            float fx = sff[m2 * 3 + 0], fy = sff[m2 * 3 + 1], fz = sff[m2 * 3 + 2];
            out[9 + m2] = fx * fx + fy * fy + fz * fz;
        }
    }
    if (a < NMOL * 3) out[13 + a] = -2.f * sfn[a];
}

extern "C" void kernel_launch(void* const* d_in, const int* in_sizes, int n_in,
                              void* d_out, int out_size) {
    const float* R      = (const float*)d_in[0];
    const float* shift  = (const float*)d_in[1];
    const float* q      = (const float*)d_in[2];
    const float* off    = (const float*)d_in[3];
    const float* cell   = (const float*)d_in[4];
    const float* recip  = (const float*)d_in[5];
    const float* r0_ij  = (const float*)d_in[6];
    const float* n_ij   = (const float*)d_in[7];
    const int*   idx_i  = (const int*)d_in[8];
    const int*   idx_j  = (const int*)d_in[9];
    const int*   idx_m  = (const int*)d_in[10];
    const int*   isf    = (const int*)d_in[11];
    float* out = (float*)d_out;

    k_prep<<<1, 256>>>(R, shift, idx_m, isf);
    k_main<<<NBLK_PAIR + NPAIRS / 256, 256>>>(q, cell, recip, off, r0_ij, n_ij,
                                              idx_i, idx_j, idx_m);
    k_fin<<<1, 256>>>(q, idx_m, isf, out);
}